// round 3
// baseline (speedup 1.0000x reference)
#include <cuda_runtime.h>
#include <cuda_bf16.h>
#include <mma.h>
#include <math.h>

using namespace nvcuda;

// ---------------- problem constants ----------------
#define B_   32
#define P_   2048
#define D_   1024
#define TD_  768
#define PR_  512
#define EPS_ 1e-5f

// ---------------- device scratch (no cudaMalloc allowed) ----------------
__device__ __nv_bfloat16 g_qh[(size_t)B_ * P_ * D_];   // 128 MB
__device__ __nv_bfloat16 g_kh[(size_t)B_ * P_ * D_];   // 128 MB
__device__ float         g_v [(size_t)B_ * P_ * D_];   // 256 MB
__device__ float g_scores[(size_t)B_ * P_ * P_];       // 512 MB (attn in-place)
__device__ float g_weighted[B_ * D_];
__device__ float g_feats[4 * B_ * PR_];

// ============================================================
// GEMM 1: qkv = X @ W + b   (tf32, 128x128 CTA tile, K-tile 16,
// double-buffered, register prefetch). q,k written as bf16, v as f32.
// X: [65536,1024] f32, W: [1024,1024] f32.
// ============================================================
#define G1_LDA 20    // 16 + 4 pad
#define G1_LDB 132   // 128 + 4 pad

__global__ __launch_bounds__(256) void gemm_qkv_kernel(
    const float* __restrict__ X,
    const float* __restrict__ Wq, const float* __restrict__ Wk, const float* __restrict__ Wv,
    const float* __restrict__ bq, const float* __restrict__ bk, const float* __restrict__ bv,
    __nv_bfloat16* __restrict__ qh, __nv_bfloat16* __restrict__ kh,
    float* __restrict__ v)
{
    __shared__ __align__(16) float As[2][128 * G1_LDA];
    __shared__ __align__(16) float Bs[2][16 * G1_LDB];

    const int z = blockIdx.z;
    const float* W = (z == 0) ? Wq : (z == 1) ? Wk : Wv;
    const float* bias = (z == 0) ? bq : (z == 1) ? bk : bv;

    const int m0 = blockIdx.y * 128;
    const int n0 = blockIdx.x * 128;

    const int tid = threadIdx.x;
    const int wid = tid >> 5, lane = tid & 31;
    const int wm = wid >> 2;      // 0..1 -> 64 rows each
    const int wn = wid & 3;       // 0..3 -> 32 cols each

    wmma::fragment<wmma::accumulator, 16, 16, 8, float> acc[4][2];
#pragma unroll
    for (int i = 0; i < 4; i++)
#pragma unroll
        for (int j = 0; j < 2; j++) wmma::fill_fragment(acc[i][j], 0.0f);

    // indices for cooperative loads (2 float4 each for A and B per stage)
    const int ar0 = tid >> 2,        ac0 = (tid & 3) * 4;        // A: t in [0,256)
    const int ar1 = (tid + 256) >> 2, ac1 = ((tid + 256) & 3) * 4;
    const int br0 = tid >> 5,        bc0 = (tid & 31) * 4;       // B: t in [0,256)
    const int br1 = (tid + 256) >> 5, bc1 = ((tid + 256) & 31) * 4;

    // preload tile 0
    {
        *(float4*)(&As[0][ar0 * G1_LDA + ac0]) = *(const float4*)(X + (size_t)(m0 + ar0) * D_ + ac0);
        *(float4*)(&As[0][ar1 * G1_LDA + ac1]) = *(const float4*)(X + (size_t)(m0 + ar1) * D_ + ac1);
        *(float4*)(&Bs[0][br0 * G1_LDB + bc0]) = *(const float4*)(W + (size_t)br0 * D_ + n0 + bc0);
        *(float4*)(&Bs[0][br1 * G1_LDB + bc1]) = *(const float4*)(W + (size_t)br1 * D_ + n0 + bc1);
    }
    __syncthreads();

    const int T = D_ / 16;
    int buf = 0;
    float4 pa0, pa1, pb0, pb1;
    for (int t = 0; t < T; t++) {
        const int kb_next = (t + 1) * 16;
        if (t + 1 < T) {
            pa0 = *(const float4*)(X + (size_t)(m0 + ar0) * D_ + kb_next + ac0);
            pa1 = *(const float4*)(X + (size_t)(m0 + ar1) * D_ + kb_next + ac1);
            pb0 = *(const float4*)(W + (size_t)(kb_next + br0) * D_ + n0 + bc0);
            pb1 = *(const float4*)(W + (size_t)(kb_next + br1) * D_ + n0 + bc1);
        }
#pragma unroll
        for (int kk = 0; kk < 16; kk += 8) {
            wmma::fragment<wmma::matrix_a, 16, 16, 8, wmma::precision::tf32, wmma::row_major> af[4];
            wmma::fragment<wmma::matrix_b, 16, 16, 8, wmma::precision::tf32, wmma::row_major> bf[2];
#pragma unroll
            for (int mi = 0; mi < 4; mi++) {
                wmma::load_matrix_sync(af[mi], &As[buf][(wm * 64 + mi * 16) * G1_LDA + kk], G1_LDA);
#pragma unroll
                for (int e = 0; e < af[mi].num_elements; e++)
                    af[mi].x[e] = wmma::__float_to_tf32(af[mi].x[e]);
            }
#pragma unroll
            for (int ni = 0; ni < 2; ni++) {
                wmma::load_matrix_sync(bf[ni], &Bs[buf][kk * G1_LDB + wn * 32 + ni * 16], G1_LDB);
#pragma unroll
                for (int e = 0; e < bf[ni].num_elements; e++)
                    bf[ni].x[e] = wmma::__float_to_tf32(bf[ni].x[e]);
            }
#pragma unroll
            for (int mi = 0; mi < 4; mi++)
#pragma unroll
                for (int ni = 0; ni < 2; ni++)
                    wmma::mma_sync(acc[mi][ni], af[mi], bf[ni], acc[mi][ni]);
        }
        if (t + 1 < T) {
            int nb = buf ^ 1;
            *(float4*)(&As[nb][ar0 * G1_LDA + ac0]) = pa0;
            *(float4*)(&As[nb][ar1 * G1_LDA + ac1]) = pa1;
            *(float4*)(&Bs[nb][br0 * G1_LDB + bc0]) = pb0;
            *(float4*)(&Bs[nb][br1 * G1_LDB + bc1]) = pb1;
        }
        __syncthreads();
        buf ^= 1;
    }

    // epilogue: stage per-warp 16x16 frags through smem, add bias, write
    float* stage = &As[0][0] + wid * 256;
#pragma unroll
    for (int mi = 0; mi < 4; mi++)
#pragma unroll
        for (int ni = 0; ni < 2; ni++) {
            wmma::store_matrix_sync(stage, acc[mi][ni], 16, wmma::mem_row_major);
            __syncwarp();
            int gm = m0 + wm * 64 + mi * 16;
            int gn = n0 + wn * 32 + ni * 16;
#pragma unroll
            for (int e = lane; e < 256; e += 32) {
                int r = e >> 4, c = e & 15;
                float val = stage[e] + bias[gn + c];
                size_t idx = (size_t)(gm + r) * D_ + gn + c;
                if (z == 0)      qh[idx] = __float2bfloat16(val);
                else if (z == 1) kh[idx] = __float2bfloat16(val);
                else             v[idx]  = val;
            }
            __syncwarp();
        }
}

// ============================================================
// GEMM 2: scores = q @ k^T   (bf16, per batch, 128x128 CTA tile,
// K-tile 32, double buffered). Raw accums to global; scale folded
// into softmax.
// ============================================================
#define G2_LD 40     // 32 + 8 pad (bf16 elems)

__global__ __launch_bounds__(256) void gemm_scores_kernel(
    const __nv_bfloat16* __restrict__ qh, const __nv_bfloat16* __restrict__ kh,
    float* __restrict__ sc)
{
    __shared__ __align__(16) __nv_bfloat16 As[2][128 * G2_LD];
    __shared__ __align__(16) __nv_bfloat16 Bs[2][128 * G2_LD];

    const int b = blockIdx.z;
    const __nv_bfloat16* A = qh + (size_t)b * P_ * D_;
    const __nv_bfloat16* Bk = kh + (size_t)b * P_ * D_;
    float* C = sc + (size_t)b * P_ * P_;

    const int m0 = blockIdx.y * 128;
    const int n0 = blockIdx.x * 128;

    const int tid = threadIdx.x;
    const int wid = tid >> 5;
    const int wm = wid >> 2, wn = wid & 3;

    wmma::fragment<wmma::accumulator, 16, 16, 16, float> acc[4][2];
#pragma unroll
    for (int i = 0; i < 4; i++)
#pragma unroll
        for (int j = 0; j < 2; j++) wmma::fill_fragment(acc[i][j], 0.0f);

    // tile = 128 rows x 32 bf16 = 1024 uint2 (4 bf16 each); 4 per thread
    // thread handles t = tid + 256*i : r = t>>3, c = (t&7)*4
#pragma unroll
    const int T = D_ / 32;
    // preload tile 0
#pragma unroll
    for (int i = 0; i < 4; i++) {
        int t = tid + 256 * i;
        int r = t >> 3, c = (t & 7) * 4;
        *(uint2*)(&As[0][r * G2_LD + c]) = *(const uint2*)(A + (size_t)(m0 + r) * D_ + c);
        *(uint2*)(&Bs[0][r * G2_LD + c]) = *(const uint2*)(Bk + (size_t)(n0 + r) * D_ + c);
    }
    __syncthreads();

    int buf = 0;
    uint2 pa[4], pb[4];
    for (int t = 0; t < T; t++) {
        const int kb_next = (t + 1) * 32;
        if (t + 1 < T) {
#pragma unroll
            for (int i = 0; i < 4; i++) {
                int tt = tid + 256 * i;
                int r = tt >> 3, c = (tt & 7) * 4;
                pa[i] = *(const uint2*)(A + (size_t)(m0 + r) * D_ + kb_next + c);
                pb[i] = *(const uint2*)(Bk + (size_t)(n0 + r) * D_ + kb_next + c);
            }
        }
#pragma unroll
        for (int kk = 0; kk < 32; kk += 16) {
            wmma::fragment<wmma::matrix_a, 16, 16, 16, __nv_bfloat16, wmma::row_major> af[4];
            wmma::fragment<wmma::matrix_b, 16, 16, 16, __nv_bfloat16, wmma::col_major> bf[2];
#pragma unroll
            for (int mi = 0; mi < 4; mi++)
                wmma::load_matrix_sync(af[mi], &As[buf][(wm * 64 + mi * 16) * G2_LD + kk], G2_LD);
#pragma unroll
            for (int ni = 0; ni < 2; ni++)
                wmma::load_matrix_sync(bf[ni], &Bs[buf][(wn * 32 + ni * 16) * G2_LD + kk], G2_LD);
#pragma unroll
            for (int mi = 0; mi < 4; mi++)
#pragma unroll
                for (int ni = 0; ni < 2; ni++)
                    wmma::mma_sync(acc[mi][ni], af[mi], bf[ni], acc[mi][ni]);
        }
        if (t + 1 < T) {
            int nb = buf ^ 1;
#pragma unroll
            for (int i = 0; i < 4; i++) {
                int tt = tid + 256 * i;
                int r = tt >> 3, c = (tt & 7) * 4;
                *(uint2*)(&As[nb][r * G2_LD + c]) = pa[i];
                *(uint2*)(&Bs[nb][r * G2_LD + c]) = pb[i];
            }
        }
        __syncthreads();
        buf ^= 1;
    }

    // epilogue: raw accumulators straight to global
#pragma unroll
    for (int mi = 0; mi < 4; mi++)
#pragma unroll
        for (int ni = 0; ni < 2; ni++) {
            int gm = m0 + wm * 64 + mi * 16;
            int gn = n0 + wn * 32 + ni * 16;
            wmma::store_matrix_sync(C + (size_t)gm * P_ + gn, acc[mi][ni], P_, wmma::mem_row_major);
        }
}

// ---------------- softmax over rows, in place (scale folded in) ----------------
__global__ __launch_bounds__(256) void softmax_rows_kernel(float* __restrict__ sc, float scale)
{
    int b = blockIdx.y;
    int wid = threadIdx.x >> 5, lane = threadIdx.x & 31;
    int row = blockIdx.x * 8 + wid;
    float* rp = sc + ((size_t)b * P_ + row) * P_;

    float vals[64];
#pragma unroll
    for (int i = 0; i < 64; i++) vals[i] = rp[lane + 32 * i] * scale;

    float m = -INFINITY;
#pragma unroll
    for (int i = 0; i < 64; i++) m = fmaxf(m, vals[i]);
#pragma unroll
    for (int o = 16; o > 0; o >>= 1) m = fmaxf(m, __shfl_xor_sync(0xFFFFFFFFu, m, o));

    float s = 0.f;
#pragma unroll
    for (int i = 0; i < 64; i++) { vals[i] = __expf(vals[i] - m); s += vals[i]; }
#pragma unroll
    for (int o = 16; o > 0; o >>= 1) s += __shfl_xor_sync(0xFFFFFFFFu, s, o);

    float rinv = 1.f / s;
#pragma unroll
    for (int i = 0; i < 64; i++) rp[lane + 32 * i] = vals[i] * rinv;
}

// ---------------- column mean of attn -> attn_weights ----------------
__global__ __launch_bounds__(256) void colsum_kernel(const float* __restrict__ sc, float* __restrict__ aw)
{
    int b = blockIdx.y;
    int q = blockIdx.x * 256 + threadIdx.x;
    const float* base = sc + (size_t)b * P_ * P_ + q;
    float acc = 0.f;
    for (int p = 0; p < P_; p++) acc += base[(size_t)p * P_];
    aw[b * P_ + q] = acc * (1.f / (float)P_);
}

// ---------------- weighted = aw @ v ----------------
__global__ void zero_kernel(float* p) { p[blockIdx.x * blockDim.x + threadIdx.x] = 0.f; }

__global__ __launch_bounds__(1024) void weighted_kernel(
    const float* __restrict__ aw, const float* __restrict__ v, float* __restrict__ wt)
{
    int b = blockIdx.y;
    int qc = blockIdx.x * 256;
    __shared__ float s_aw[256];
    if (threadIdx.x < 256) s_aw[threadIdx.x] = aw[b * P_ + qc + threadIdx.x];
    __syncthreads();
    float acc = 0.f;
    const float* vb = v + ((size_t)b * P_ + qc) * D_ + threadIdx.x;
#pragma unroll 4
    for (int qq = 0; qq < 256; qq++) acc += s_aw[qq] * vb[(size_t)qq * D_];
    atomicAdd(&wt[b * D_ + threadIdx.x], acc);
}

// ---------------- fused MLP + L2 normalize ----------------
__device__ __forceinline__ float block_sum(float v, float* red)
{
#pragma unroll
    for (int o = 16; o > 0; o >>= 1) v += __shfl_xor_sync(0xFFFFFFFFu, v, o);
    int w = threadIdx.x >> 5, l = threadIdx.x & 31;
    if (l == 0) red[w] = v;
    __syncthreads();
    if (w == 0) {
        float r = (threadIdx.x < (blockDim.x >> 5)) ? red[threadIdx.x] : 0.f;
#pragma unroll
        for (int o = 16; o > 0; o >>= 1) r += __shfl_xor_sync(0xFFFFFFFFu, r, o);
        if (l == 0) red[0] = r;
    }
    __syncthreads();
    float out = red[0];
    __syncthreads();
    return out;
}

__global__ __launch_bounds__(1024) void mlp_kernel(
    const float* __restrict__ wt, const float* __restrict__ thum, const float* __restrict__ text,
    const float* peW1, const float* peb1, const float* peg, const float* pebt,
    const float* peW2, const float* peb2,
    const float* teW1, const float* teb1, const float* teg, const float* tebt,
    const float* teW2, const float* teb2,
    const float* thW1, const float* thb1, const float* thg, const float* thbt,
    const float* thW2, const float* thb2,
    float* __restrict__ feats)
{
    int row = blockIdx.x, job = blockIdx.y;
    const float *x, *W1, *b1, *g, *bt, *W2, *b2;
    int din;
    if (job == 0)      { x = wt + row * D_;                din = D_;  W1 = peW1; b1 = peb1; g = peg; bt = pebt; W2 = peW2; b2 = peb2; }
    else if (job == 1) { x = thum + row * D_;              din = D_;  W1 = thW1; b1 = thb1; g = thg; bt = thbt; W2 = thW2; b2 = thb2; }
    else if (job == 2) { x = text + row * 3 * TD_ + TD_;   din = TD_; W1 = teW1; b1 = teb1; g = teg; bt = tebt; W2 = teW2; b2 = teb2; }
    else               { x = text + row * 3 * TD_ + 2*TD_; din = TD_; W1 = teW1; b1 = teb1; g = teg; bt = tebt; W2 = teW2; b2 = teb2; }

    __shared__ float xs[1024];
    __shared__ float hs[1024];
    __shared__ float red[32];
    int tid = threadIdx.x;
    if (tid < din) xs[tid] = x[tid];
    __syncthreads();

    float acc = b1[tid];
    for (int i = 0; i < din; i++) acc += xs[i] * W1[(size_t)i * 1024 + tid];
    float h = fmaxf(acc, 0.f);

    float s1 = block_sum(h, red);
    float s2 = block_sum(h * h, red);
    float mu = s1 * (1.f / 1024.f);
    float var = s2 * (1.f / 1024.f) - mu * mu;
    float rstd = rsqrtf(var + EPS_);
    hs[tid] = (h - mu) * rstd * g[tid] + bt[tid];
    __syncthreads();

    float o = 0.f;
    if (tid < PR_) {
        float a2 = b2[tid];
        for (int i = 0; i < 1024; i++) a2 += hs[i] * W2[(size_t)i * PR_ + tid];
        o = fmaxf(a2, 0.f);
    }
    float nrm = block_sum(o * o, red);
    if (tid < PR_) feats[((size_t)job * B_ + row) * PR_ + tid] = o * rsqrtf(nrm);
}

// ---------------- logits ----------------
__global__ void logits_kernel(const float* __restrict__ feats, const float* __restrict__ ls_p,
                              float* __restrict__ out)
{
    int j = threadIdx.x, i = threadIdx.y;
    float ls = expf(ls_p[0]);
    const float* pf = feats;                 // patch_features
    const float* tf = feats + 1 * B_ * PR_;  // thum_features
    const float* of = feats + 2 * B_ * PR_;  // text_orgp
    const float* hf = feats + 3 * B_ * PR_;  // text_hist
    float lt = 0.f, lp = 0.f;
    for (int d = 0; d < PR_; d++) {
        lt += tf[i * PR_ + d] * of[j * PR_ + d];
        lp += pf[i * PR_ + d] * hf[j * PR_ + d];
    }
    lt *= ls; lp *= ls;
    out[0 * 1024 + i * 32 + j] = lt;
    out[1 * 1024 + i * 32 + j] = lp;
    out[2 * 1024 + j * 32 + i] = lt;
    out[3 * 1024 + j * 32 + i] = lp;
}

// ---------------- launch ----------------
extern "C" void kernel_launch(void* const* d_in, const int* in_sizes, int n_in,
                              void* d_out, int out_size)
{
    const float* thum  = (const float*)d_in[0];
    const float* patch = (const float*)d_in[1];
    const float* text  = (const float*)d_in[2];
    const float* Wq = (const float*)d_in[3];  const float* bq = (const float*)d_in[4];
    const float* Wk = (const float*)d_in[5];  const float* bk = (const float*)d_in[6];
    const float* Wv = (const float*)d_in[7];  const float* bv = (const float*)d_in[8];
    const float* peW1 = (const float*)d_in[9];  const float* peb1 = (const float*)d_in[10];
    const float* peg  = (const float*)d_in[11]; const float* pebt = (const float*)d_in[12];
    const float* peW2 = (const float*)d_in[13]; const float* peb2 = (const float*)d_in[14];
    const float* teW1 = (const float*)d_in[15]; const float* teb1 = (const float*)d_in[16];
    const float* teg  = (const float*)d_in[17]; const float* tebt = (const float*)d_in[18];
    const float* teW2 = (const float*)d_in[19]; const float* teb2 = (const float*)d_in[20];
    const float* thW1 = (const float*)d_in[21]; const float* thb1 = (const float*)d_in[22];
    const float* thg  = (const float*)d_in[23]; const float* thbt = (const float*)d_in[24];
    const float* thW2 = (const float*)d_in[25]; const float* thb2 = (const float*)d_in[26];
    const float* logit_scale = (const float*)d_in[27];

    float* out = (float*)d_out;
    float* aw_out = out + 4 * 1024;   // attn_weights region

    __nv_bfloat16 *qh, *kh;
    float *v, *sc, *wt, *ft;
    cudaGetSymbolAddress((void**)&qh, g_qh);
    cudaGetSymbolAddress((void**)&kh, g_kh);
    cudaGetSymbolAddress((void**)&v,  g_v);
    cudaGetSymbolAddress((void**)&sc, g_scores);
    cudaGetSymbolAddress((void**)&wt, g_weighted);
    cudaGetSymbolAddress((void**)&ft, g_feats);

    const float scale = 1.f / 32.f;  // 1/sqrt(1024)

    // 1) q,k (bf16), v (f32) = X @ W* + b*
    gemm_qkv_kernel<<<dim3(D_ / 128, (B_ * P_) / 128, 3), 256>>>(
        patch, Wq, Wk, Wv, bq, bk, bv, qh, kh, v);

    // 2) scores = q @ k^T (raw; scale folded into softmax)
    gemm_scores_kernel<<<dim3(P_ / 128, P_ / 128, B_), 256>>>(qh, kh, sc);

    // 3) softmax over rows (in place, applies scale)
    softmax_rows_kernel<<<dim3(P_ / 8, B_), 256>>>(sc, scale);

    // 4) attn_weights = column mean -> directly into output
    colsum_kernel<<<dim3(P_ / 256, B_), 256>>>(sc, aw_out);

    // 5) weighted = attn_weights @ v
    zero_kernel<<<B_, D_>>>(wt);
    weighted_kernel<<<dim3(P_ / 256, B_), 1024>>>(aw_out, v, wt);

    // 6) four MLPs + L2 normalize
    mlp_kernel<<<dim3(B_, 4), 1024>>>(wt, thum, text,
        peW1, peb1, peg, pebt, peW2, peb2,
        teW1, teb1, teg, tebt, teW2, teb2,
        thW1, thb1, thg, thbt, thW2, thb2, ft);

    // 7) logits (all 4 views)
    logits_kernel<<<1, dim3(32, 32)>>>(ft, logit_scale, out);
}

// round 5
// speedup vs baseline: 2.6110x; 2.6110x over previous
#include <cuda_runtime.h>
#include <cuda_bf16.h>
#include <math.h>
#include <cstdint>

#define B_ 32
#define P_ 2048
#define D_ 1024
#define TD_ 768
#define PR_ 512
#define EPS_ 1e-5f

__device__ __align__(256) __nv_bfloat16 g_xhi[(size_t)B_*P_*D_];
__device__ __align__(256) __nv_bfloat16 g_xlo[(size_t)B_*P_*D_];
__device__ __align__(256) __nv_bfloat16 g_qh[(size_t)B_*P_*D_];
__device__ __align__(256) __nv_bfloat16 g_kh[(size_t)B_*P_*D_];
__device__ __align__(256) float g_v[(size_t)B_*P_*D_];
__device__ __align__(256) __nv_bfloat16 g_wqk[2*(size_t)D_*D_];
__device__ __align__(256) __nv_bfloat16 g_wv[2*(size_t)D_*D_];
__device__ __align__(256) float g_scores[(size_t)B_*P_*P_];
__device__ float g_weighted[B_*D_];
__device__ float g_feats[4*B_*PR_];

// ---- helpers ----
__device__ __forceinline__ uint32_t smem_u32(const void* p){uint32_t a;asm("{.reg .u64 t; cvta.to.shared.u64 t,%1; cvt.u32.u64 %0,t;}":"=r"(a):"l"(p));return a;}
__device__ __forceinline__ void cpa16(uint32_t s,const void* g){asm volatile("cp.async.cg.shared.global [%0],[%1],16;"::"r"(s),"l"(g));}
__device__ __forceinline__ void cpa_commit(){asm volatile("cp.async.commit_group;");}
template<int N> __device__ __forceinline__ void cpa_wait(){asm volatile("cp.async.wait_group %0;"::"n"(N));}
__device__ __forceinline__ void ldsm4(uint32_t* r,uint32_t a){
    asm volatile("ldmatrix.sync.aligned.m8n8.x4.shared.b16 {%0,%1,%2,%3},[%4];":"=r"(r[0]),"=r"(r[1]),"=r"(r[2]),"=r"(r[3]):"r"(a));
}
__device__ __forceinline__ void ldsm4t(uint32_t* r,uint32_t a){
    asm volatile("ldmatrix.sync.aligned.m8n8.x4.trans.shared.b16 {%0,%1,%2,%3},[%4];":"=r"(r[0]),"=r"(r[1]),"=r"(r[2]),"=r"(r[3]):"r"(a));
}
__device__ __forceinline__ void mma16816(float* c,const uint32_t* a,const uint32_t* b){
    asm volatile("mma.sync.aligned.m16n8k16.row.col.f32.bf16.bf16.f32 {%0,%1,%2,%3},{%4,%5,%6,%7},{%8,%9},{%0,%1,%2,%3};"
      :"+f"(c[0]),"+f"(c[1]),"+f"(c[2]),"+f"(c[3])
      :"r"(a[0]),"r"(a[1]),"r"(a[2]),"r"(a[3]),"r"(b[0]),"r"(b[1]));
}
__device__ __forceinline__ uint32_t cvt2(float hi,float lo){uint32_t r;asm("cvt.rn.bf16x2.f32 %0,%1,%2;":"=r"(r):"f"(hi),"f"(lo));return r;}

// ---- mma.sync core: acc[128x128] += sum_p A_p[128,1024] @ B_p^T ----
// BTRANS=false: B rows = n (k-contiguous, 128x32 tile)   [scores: k-matrix]
// BTRANS=true : B rows = k (n-contiguous, 32x128 tile)   [projections: W]
#define STG_BYTES 16384

template<bool BTRANS, int NP>
__device__ __forceinline__ void mm_core(
    const __nv_bfloat16* const* Ap, const __nv_bfloat16* const* Bp,
    float acc[4][4][4], char* smem)
{
    const int tid=threadIdx.x, wid=tid>>5, lane=tid&31;
    const int wm=wid>>2, wn=wid&3;
    const uint32_t sb=smem_u32(smem);

    auto fill=[&](int stg,int tau){
        int p=tau>>5, t=tau&31;
        const char* Ab=(const char*)Ap[p];
        const char* Bb=(const char*)Bp[p];
        uint32_t as=sb+stg*STG_BYTES, bs=as+8192;
#pragma unroll
        for(int i=0;i<2;i++){
            int j=tid+256*i, r=j>>2, c=j&3;
            cpa16(as + r*64 + ((c^((r>>1)&3))<<4), Ab + (size_t)r*2048 + t*64 + c*16);
        }
        if(!BTRANS){
#pragma unroll
            for(int i=0;i<2;i++){
                int j=tid+256*i, r=j>>2, c=j&3;
                cpa16(bs + r*64 + ((c^((r>>1)&3))<<4), Bb + (size_t)r*2048 + t*64 + c*16);
            }
        } else {
#pragma unroll
            for(int i=0;i<2;i++){
                int j=tid+256*i, r=j>>4, c=j&15;
                cpa16(bs + r*256 + ((c^(r&7))<<4), Bb + (size_t)(t*32+r)*2048 + c*16);
            }
        }
        cpa_commit();
    };

    const int T=NP*32;
    fill(0,0); fill(1,1);
    for(int tau=0;tau<T;tau++){
        int s=tau%3;
        cpa_wait<1>();
        __syncthreads();
        if(tau+2<T) fill((tau+2)%3, tau+2);
        uint32_t as=sb+s*STG_BYTES, bs=as+8192;
#pragma unroll
        for(int k0=0;k0<32;k0+=16){
            uint32_t a[4][4];
#pragma unroll
            for(int mf=0;mf<4;mf++){
                int r=wm*64+mf*16+(lane&15);
                int c=(k0>>3)+(lane>>4);
                ldsm4(a[mf], as + r*64 + ((c^((r>>1)&3))<<4));
            }
            uint32_t b[4][2];
            if(!BTRANS){
#pragma unroll
                for(int nf2=0;nf2<2;nf2++){
                    int r=wn*32+nf2*16+8*((lane>>3)&1)+(lane&7);
                    int c=(k0>>3)+(lane>>4);
                    uint32_t q[4]; ldsm4(q, bs + r*64 + ((c^((r>>1)&3))<<4));
                    b[nf2*2][0]=q[0]; b[nf2*2][1]=q[2]; b[nf2*2+1][0]=q[1]; b[nf2*2+1][1]=q[3];
                }
            } else {
#pragma unroll
                for(int nf2=0;nf2<2;nf2++){
                    int r=k0+8*((lane>>3)&1)+(lane&7);
                    int c=((wn*32+nf2*16)>>3)+(lane>>4);
                    uint32_t q[4]; ldsm4t(q, bs + r*256 + ((c^(r&7))<<4));
                    b[nf2*2][0]=q[0]; b[nf2*2][1]=q[1]; b[nf2*2+1][0]=q[2]; b[nf2*2+1][1]=q[3];
                }
            }
#pragma unroll
            for(int mf=0;mf<4;mf++)
#pragma unroll
                for(int nf=0;nf<4;nf++)
                    mma16816(acc[mf][nf], a[mf], b[nf]);
        }
    }
}

// ---- GEMM kernels ----
__global__ void __launch_bounds__(256) mm_qk(
    const __nv_bfloat16* __restrict__ Xhi, const __nv_bfloat16* __restrict__ Wqk,
    const float* __restrict__ bq, const float* __restrict__ bk,
    __nv_bfloat16* __restrict__ qh, __nv_bfloat16* __restrict__ kh)
{
    extern __shared__ __align__(1024) char smem[];
    int z=blockIdx.z;
    const __nv_bfloat16* A = Xhi + (size_t)blockIdx.y*128*D_;
    const __nv_bfloat16* Bm = Wqk + (size_t)z*D_*D_ + blockIdx.x*128;
    const __nv_bfloat16* Apl[1]={A}; const __nv_bfloat16* Bpl[1]={Bm};
    float acc[4][4][4]={};
    mm_core<true,1>(Apl,Bpl,acc,smem);
    const float* bias = z? bk:bq;
    __nv_bfloat16* outp = z? kh:qh;
    int wid=threadIdx.x>>5, lane=threadIdx.x&31, wm=wid>>2, wn=wid&3;
    size_t m0=(size_t)blockIdx.y*128 + wm*64 + lane/4;
    int n0=blockIdx.x*128 + wn*32 + (lane%4)*2;
#pragma unroll
    for(int mf=0;mf<4;mf++)
#pragma unroll
    for(int nf=0;nf<4;nf++){
        int n=n0+nf*8; size_t m=m0+mf*16;
        float b0=bias[n], b1=bias[n+1];
        *(uint32_t*)(outp+m*D_+n)     = cvt2(acc[mf][nf][1]+b1, acc[mf][nf][0]+b0);
        *(uint32_t*)(outp+(m+8)*D_+n) = cvt2(acc[mf][nf][3]+b1, acc[mf][nf][2]+b0);
    }
}

__global__ void __launch_bounds__(256) mm_v(
    const __nv_bfloat16* __restrict__ Xhi, const __nv_bfloat16* __restrict__ Xlo,
    const __nv_bfloat16* __restrict__ Wv2, const float* __restrict__ bv,
    float* __restrict__ v)
{
    extern __shared__ __align__(1024) char smem[];
    const __nv_bfloat16* A = Xhi + (size_t)blockIdx.y*128*D_;
    const __nv_bfloat16* Al = Xlo + (size_t)blockIdx.y*128*D_;
    const __nv_bfloat16* Whi = Wv2 + blockIdx.x*128;
    const __nv_bfloat16* Wlo = Wv2 + (size_t)D_*D_ + blockIdx.x*128;
    const __nv_bfloat16* Apl[3]={A,Al,A}; const __nv_bfloat16* Bpl[3]={Whi,Whi,Wlo};
    float acc[4][4][4]={};
    mm_core<true,3>(Apl,Bpl,acc,smem);
    int wid=threadIdx.x>>5, lane=threadIdx.x&31, wm=wid>>2, wn=wid&3;
    size_t m0=(size_t)blockIdx.y*128 + wm*64 + lane/4;
    int n0=blockIdx.x*128 + wn*32 + (lane%4)*2;
#pragma unroll
    for(int mf=0;mf<4;mf++)
#pragma unroll
    for(int nf=0;nf<4;nf++){
        int n=n0+nf*8; size_t m=m0+mf*16;
        float b0=bv[n], b1=bv[n+1];
        *(float2*)(v+m*D_+n)     = make_float2(acc[mf][nf][0]+b0, acc[mf][nf][1]+b1);
        *(float2*)(v+(m+8)*D_+n) = make_float2(acc[mf][nf][2]+b0, acc[mf][nf][3]+b1);
    }
}

__global__ void __launch_bounds__(256) mm_sc(
    const __nv_bfloat16* __restrict__ qh, const __nv_bfloat16* __restrict__ kh,
    float* __restrict__ sc)
{
    extern __shared__ __align__(1024) char smem[];
    int z=blockIdx.z;
    const __nv_bfloat16* A = qh + (size_t)z*P_*D_ + (size_t)blockIdx.y*128*D_;
    const __nv_bfloat16* Bm = kh + (size_t)z*P_*D_ + (size_t)blockIdx.x*128*D_;
    const __nv_bfloat16* Apl[1]={A}; const __nv_bfloat16* Bpl[1]={Bm};
    float acc[4][4][4]={};
    mm_core<false,1>(Apl,Bpl,acc,smem);
    int wid=threadIdx.x>>5, lane=threadIdx.x&31, wm=wid>>2, wn=wid&3;
    size_t m0=(size_t)blockIdx.y*128 + wm*64 + lane/4;
    int n0=blockIdx.x*128 + wn*32 + (lane%4)*2;
    float* C = sc + (size_t)z*P_*P_;
#pragma unroll
    for(int mf=0;mf<4;mf++)
#pragma unroll
    for(int nf=0;nf<4;nf++){
        int n=n0+nf*8; size_t m=m0+mf*16;
        *(float2*)(C+m*P_+n)     = make_float2(acc[mf][nf][0], acc[mf][nf][1]);
        *(float2*)(C+(m+8)*P_+n) = make_float2(acc[mf][nf][2], acc[mf][nf][3]);
    }
}

// ---- prep kernels ----
__global__ void split_x(const float4* __restrict__ X, uint2* __restrict__ hi, uint2* __restrict__ lo)
{
    size_t i=(size_t)blockIdx.x*1024+threadIdx.x;
    float4 x=X[i];
    __nv_bfloat16 h[4], l[4];
    const float* xp=&x.x;
#pragma unroll
    for(int j=0;j<4;j++){ h[j]=__float2bfloat16(xp[j]); l[j]=__float2bfloat16(xp[j]-__bfloat162float(h[j])); }
    hi[i]=*(uint2*)h; lo[i]=*(uint2*)l;
}

__global__ void conv_wqk(const float* __restrict__ Wq,const float* __restrict__ Wk,__nv_bfloat16* __restrict__ out)
{
    size_t i=(size_t)blockIdx.x*1024+threadIdx.x;
    const size_t M=(size_t)D_*D_;
    out[i]=__float2bfloat16(i<M ? Wq[i] : Wk[i-M]);
}

__global__ void conv_wv(const float* __restrict__ Wv,__nv_bfloat16* __restrict__ out)
{
    size_t i=(size_t)blockIdx.x*1024+threadIdx.x;
    float w=Wv[i];
    __nv_bfloat16 h=__float2bfloat16(w);
    out[i]=h;
    out[(size_t)D_*D_+i]=__float2bfloat16(w-__bfloat162float(h));
}

__global__ void zero_f(float* p){ p[(size_t)blockIdx.x*blockDim.x+threadIdx.x]=0.f; }

// ---- fused softmax + column-mean accumulation ----
__global__ __launch_bounds__(256) void softmax_colsum(const float* __restrict__ sc, float* __restrict__ aw, float scale)
{
    __shared__ float colacc[P_];
    int b=blockIdx.y, wid=threadIdx.x>>5, lane=threadIdx.x&31, tid=threadIdx.x;
#pragma unroll
    for(int i=0;i<8;i++) colacc[tid+256*i]=0.f;
    __syncthreads();

    const float* rp=sc+((size_t)b*P_+blockIdx.x*8+wid)*P_;
    float v[64];
#pragma unroll
    for(int i=0;i<64;i++) v[i]=rp[lane+32*i]*scale;
    float m=-INFINITY;
#pragma unroll
    for(int i=0;i<64;i++) m=fmaxf(m,v[i]);
#pragma unroll
    for(int o=16;o>0;o>>=1) m=fmaxf(m,__shfl_xor_sync(~0u,m,o));
    float s=0.f;
#pragma unroll
    for(int i=0;i<64;i++){ v[i]=__expf(v[i]-m); s+=v[i]; }
#pragma unroll
    for(int o=16;o>0;o>>=1) s+=__shfl_xor_sync(~0u,s,o);
    float rinv=1.f/s;
#pragma unroll
    for(int i=0;i<64;i++) atomicAdd(&colacc[lane+32*i], v[i]*rinv);
    __syncthreads();
#pragma unroll
    for(int i=0;i<8;i++) atomicAdd(&aw[b*P_+tid+256*i], colacc[tid+256*i]*(1.f/(float)P_));
}

// ---- weighted = aw @ v ----
__global__ __launch_bounds__(1024) void weighted_kernel(
    const float* __restrict__ aw,const float* __restrict__ v,float* __restrict__ wt)
{
    int b=blockIdx.y, qc=blockIdx.x*256;
    __shared__ float s_aw[256];
    if(threadIdx.x<256) s_aw[threadIdx.x]=aw[b*P_+qc+threadIdx.x];
    __syncthreads();
    float acc=0.f;
    const float* vb=v+((size_t)b*P_+qc)*D_+threadIdx.x;
#pragma unroll 4
    for(int q=0;q<256;q++) acc+=s_aw[q]*vb[(size_t)q*D_];
    atomicAdd(&wt[b*D_+threadIdx.x],acc);
}

__device__ __forceinline__ float block_sum(float v,float* red)
{
#pragma unroll
    for(int o=16;o>0;o>>=1) v+=__shfl_xor_sync(~0u,v,o);
    int w=threadIdx.x>>5,l=threadIdx.x&31;
    if(l==0) red[w]=v;
    __syncthreads();
    if(w==0){
        float r=(threadIdx.x<(blockDim.x>>5))?red[threadIdx.x]:0.f;
#pragma unroll
        for(int o=16;o>0;o>>=1) r+=__shfl_xor_sync(~0u,r,o);
        if(l==0) red[0]=r;
    }
    __syncthreads();
    float out=red[0];
    __syncthreads();
    return out;
}

__global__ __launch_bounds__(1024) void mlp_kernel(
    const float* __restrict__ wt,const float* __restrict__ thum,const float* __restrict__ text,
    const float* peW1,const float* peb1,const float* peg,const float* pebt,const float* peW2,const float* peb2,
    const float* teW1,const float* teb1,const float* teg,const float* tebt,const float* teW2,const float* teb2,
    const float* thW1,const float* thb1,const float* thg,const float* thbt,const float* thW2,const float* thb2,
    float* __restrict__ feats)
{
    int row=blockIdx.x, job=blockIdx.y;
    const float *x,*W1,*b1,*g,*bt,*W2,*b2; int din;
    if(job==0){x=wt+row*D_;din=D_;W1=peW1;b1=peb1;g=peg;bt=pebt;W2=peW2;b2=peb2;}
    else if(job==1){x=thum+row*D_;din=D_;W1=thW1;b1=thb1;g=thg;bt=thbt;W2=thW2;b2=thb2;}
    else if(job==2){x=text+row*3*TD_+TD_;din=TD_;W1=teW1;b1=teb1;g=teg;bt=tebt;W2=teW2;b2=teb2;}
    else{x=text+row*3*TD_+2*TD_;din=TD_;W1=teW1;b1=teb1;g=teg;bt=tebt;W2=teW2;b2=teb2;}
    __shared__ float xs[1024], hs[1024], red[32];
    int tid=threadIdx.x;
    if(tid<din) xs[tid]=x[tid];
    __syncthreads();
    float acc=b1[tid];
    for(int i=0;i<din;i++) acc+=xs[i]*W1[(size_t)i*1024+tid];
    float h=fmaxf(acc,0.f);
    float s1=block_sum(h,red), s2=block_sum(h*h,red);
    float mu=s1*(1.f/1024.f), var=s2*(1.f/1024.f)-mu*mu, rstd=rsqrtf(var+EPS_);
    hs[tid]=(h-mu)*rstd*g[tid]+bt[tid];
    __syncthreads();
    float o=0.f;
    if(tid<PR_){
        float a2=b2[tid];
        for(int i=0;i<1024;i++) a2+=hs[i]*W2[(size_t)i*PR_+tid];
        o=fmaxf(a2,0.f);
    }
    float nrm=block_sum(o*o,red);
    if(tid<PR_) feats[((size_t)job*B_+row)*PR_+tid]=o*rsqrtf(nrm);
}

__global__ void logits_kernel(const float* __restrict__ feats,const float* __restrict__ ls_p,float* __restrict__ out)
{
    int j=threadIdx.x,i=threadIdx.y;
    float ls=expf(ls_p[0]);
    const float* pf=feats; const float* tf=feats+B_*PR_;
    const float* of=feats+2*B_*PR_; const float* hf=feats+3*B_*PR_;
    float lt=0.f,lp=0.f;
    for(int d=0;d<PR_;d++){ lt+=tf[i*PR_+d]*of[j*PR_+d]; lp+=pf[i*PR_+d]*hf[j*PR_+d]; }
    lt*=ls; lp*=ls;
    out[i*32+j]=lt; out[1024+i*32+j]=lp; out[2048+j*32+i]=lt; out[3072+j*32+i]=lp;
}

extern "C" void kernel_launch(void* const* d_in, const int* in_sizes, int n_in,
                              void* d_out, int out_size)
{
    const float* thum=(const float*)d_in[0];
    const float* patch=(const float*)d_in[1];
    const float* text=(const float*)d_in[2];
    const float* Wq=(const float*)d_in[3]; const float* bq=(const float*)d_in[4];
    const float* Wk=(const float*)d_in[5]; const float* bk=(const float*)d_in[6];
    const float* Wv=(const float*)d_in[7]; const float* bv=(const float*)d_in[8];
    const float* peW1=(const float*)d_in[9];  const float* peb1=(const float*)d_in[10];
    const float* peg =(const float*)d_in[11]; const float* pebt=(const float*)d_in[12];
    const float* peW2=(const float*)d_in[13]; const float* peb2=(const float*)d_in[14];
    const float* teW1=(const float*)d_in[15]; const float* teb1=(const float*)d_in[16];
    const float* teg =(const float*)d_in[17]; const float* tebt=(const float*)d_in[18];
    const float* teW2=(const float*)d_in[19]; const float* teb2=(const float*)d_in[20];
    const float* thW1=(const float*)d_in[21]; const float* thb1=(const float*)d_in[22];
    const float* thg =(const float*)d_in[23]; const float* thbt=(const float*)d_in[24];
    const float* thW2=(const float*)d_in[25]; const float* thb2=(const float*)d_in[26];
    const float* logit_scale=(const float*)d_in[27];

    float* out=(float*)d_out;
    float* aw_out=out+4096;

    __nv_bfloat16 *xhi,*xlo,*qh,*kh,*wqk,*wv;
    float *v,*sc,*wtd,*ft;
    cudaGetSymbolAddress((void**)&xhi,g_xhi);
    cudaGetSymbolAddress((void**)&xlo,g_xlo);
    cudaGetSymbolAddress((void**)&qh,g_qh);
    cudaGetSymbolAddress((void**)&kh,g_kh);
    cudaGetSymbolAddress((void**)&wqk,g_wqk);
    cudaGetSymbolAddress((void**)&wv,g_wv);
    cudaGetSymbolAddress((void**)&v,g_v);
    cudaGetSymbolAddress((void**)&sc,g_scores);
    cudaGetSymbolAddress((void**)&wtd,g_weighted);
    cudaGetSymbolAddress((void**)&ft,g_feats);

    const int SMEM=3*STG_BYTES; // 48KB

    // prep
    split_x<<<16384,1024>>>((const float4*)patch,(uint2*)xhi,(uint2*)xlo);
    conv_wqk<<<2048,1024>>>(Wq,Wk,wqk);
    conv_wv<<<1024,1024>>>(Wv,wv);

    // GEMMs (mma.sync bf16)
    mm_qk<<<dim3(D_/128,(B_*P_)/128,2),256,SMEM>>>(xhi,wqk,bq,bk,qh,kh);
    mm_v <<<dim3(D_/128,(B_*P_)/128),256,SMEM>>>(xhi,xlo,wv,bv,v);
    mm_sc<<<dim3(P_/128,P_/128,B_),256,SMEM>>>(qh,kh,sc);

    // softmax + column mean (attn never materialized)
    zero_f<<<64,1024>>>(aw_out);
    softmax_colsum<<<dim3(P_/8,B_),256>>>(sc,aw_out,1.f/32.f);

    // weighted = aw @ v
    zero_f<<<32,1024>>>(wtd);
    weighted_kernel<<<dim3(P_/256,B_),1024>>>(aw_out,v,wtd);

    // MLPs + logits
    mlp_kernel<<<dim3(B_,4),1024>>>(wtd,thum,text,
        peW1,peb1,peg,pebt,peW2,peb2,
        teW1,teb1,teg,tebt,teW2,teb2,
        thW1,thb1,thg,thbt,thW2,thb2,ft);
    logits_kernel<<<1,dim3(32,32)>>>(ft,logit_scale,out);
}

// round 6
// speedup vs baseline: 3.6295x; 1.3901x over previous
#include <cuda_runtime.h>
#include <cuda_bf16.h>
#include <math.h>
#include <cstdint>

#define B_ 32
#define P_ 2048
#define D_ 1024
#define TD_ 768
#define PR_ 512
#define EPS_ 1e-5f

__device__ __align__(256) __nv_bfloat16 g_xh[(size_t)B_*P_*D_];
__device__ __align__(256) __nv_bfloat16 g_qh[(size_t)B_*P_*D_];
__device__ __align__(256) __nv_bfloat16 g_kh[(size_t)B_*P_*D_];
__device__ __align__(256) __nv_bfloat16 g_wqk[2*(size_t)D_*D_];
__device__ __align__(256) float g_scores[(size_t)B_*P_*P_];
__device__ float g_xw[B_*D_];
__device__ float g_weighted[B_*D_];
__device__ float g_feats[4*B_*PR_];

// ---- helpers ----
__device__ __forceinline__ uint32_t smem_u32(const void* p){uint32_t a;asm("{.reg .u64 t; cvta.to.shared.u64 t,%1; cvt.u32.u64 %0,t;}":"=r"(a):"l"(p));return a;}
__device__ __forceinline__ void cpa16(uint32_t s,const void* g){asm volatile("cp.async.cg.shared.global [%0],[%1],16;"::"r"(s),"l"(g));}
__device__ __forceinline__ void cpa_commit(){asm volatile("cp.async.commit_group;");}
template<int N> __device__ __forceinline__ void cpa_wait(){asm volatile("cp.async.wait_group %0;"::"n"(N));}
__device__ __forceinline__ void ldsm4(uint32_t* r,uint32_t a){
    asm volatile("ldmatrix.sync.aligned.m8n8.x4.shared.b16 {%0,%1,%2,%3},[%4];":"=r"(r[0]),"=r"(r[1]),"=r"(r[2]),"=r"(r[3]):"r"(a));
}
__device__ __forceinline__ void ldsm4t(uint32_t* r,uint32_t a){
    asm volatile("ldmatrix.sync.aligned.m8n8.x4.trans.shared.b16 {%0,%1,%2,%3},[%4];":"=r"(r[0]),"=r"(r[1]),"=r"(r[2]),"=r"(r[3]):"r"(a));
}
__device__ __forceinline__ void mma16816(float* c,const uint32_t* a,const uint32_t* b){
    asm volatile("mma.sync.aligned.m16n8k16.row.col.f32.bf16.bf16.f32 {%0,%1,%2,%3},{%4,%5,%6,%7},{%8,%9},{%0,%1,%2,%3};"
      :"+f"(c[0]),"+f"(c[1]),"+f"(c[2]),"+f"(c[3])
      :"r"(a[0]),"r"(a[1]),"r"(a[2]),"r"(a[3]),"r"(b[0]),"r"(b[1]));
}
__device__ __forceinline__ uint32_t cvt2(float hi,float lo){uint32_t r;asm("cvt.rn.bf16x2.f32 %0,%1,%2;":"=r"(r):"f"(hi),"f"(lo));return r;}

// ---- mma.sync core: acc[128x128] = A[128,1024] @ B^T ----
// BTRANS=false: B rows = n (k-contiguous)  [scores]
// BTRANS=true : B rows = k (n-contiguous)  [projections]
#define STG_BYTES 16384

template<bool BTRANS>
__device__ __forceinline__ void mm_core(
    const __nv_bfloat16* A, const __nv_bfloat16* Bm,
    float acc[4][4][4], char* smem)
{
    const int tid=threadIdx.x, wid=tid>>5, lane=tid&31;
    const int wm=wid>>2, wn=wid&3;
    const uint32_t sb=smem_u32(smem);

    auto fill=[&](int stg,int t){
        const char* Ab=(const char*)A;
        const char* Bb=(const char*)Bm;
        uint32_t as=sb+stg*STG_BYTES, bs=as+8192;
#pragma unroll
        for(int i=0;i<2;i++){
            int j=tid+256*i, r=j>>2, c=j&3;
            cpa16(as + r*64 + ((c^((r>>1)&3))<<4), Ab + (size_t)r*2048 + t*64 + c*16);
        }
        if(!BTRANS){
#pragma unroll
            for(int i=0;i<2;i++){
                int j=tid+256*i, r=j>>2, c=j&3;
                cpa16(bs + r*64 + ((c^((r>>1)&3))<<4), Bb + (size_t)r*2048 + t*64 + c*16);
            }
        } else {
#pragma unroll
            for(int i=0;i<2;i++){
                int j=tid+256*i, r=j>>4, c=j&15;
                cpa16(bs + r*256 + ((c^(r&7))<<4), Bb + (size_t)(t*32+r)*2048 + c*16);
            }
        }
        cpa_commit();
    };

    const int T=32;
    fill(0,0); fill(1,1);
    for(int tau=0;tau<T;tau++){
        int s=tau%3;
        cpa_wait<1>();
        __syncthreads();
        if(tau+2<T) fill((tau+2)%3, tau+2);
        uint32_t as=sb+s*STG_BYTES, bs=as+8192;
#pragma unroll
        for(int k0=0;k0<32;k0+=16){
            uint32_t a[4][4];
#pragma unroll
            for(int mf=0;mf<4;mf++){
                int r=wm*64+mf*16+(lane&15);
                int c=(k0>>3)+(lane>>4);
                ldsm4(a[mf], as + r*64 + ((c^((r>>1)&3))<<4));
            }
            uint32_t b[4][2];
            if(!BTRANS){
#pragma unroll
                for(int nf2=0;nf2<2;nf2++){
                    int r=wn*32+nf2*16+8*((lane>>3)&1)+(lane&7);
                    int c=(k0>>3)+(lane>>4);
                    uint32_t q[4]; ldsm4(q, bs + r*64 + ((c^((r>>1)&3))<<4));
                    b[nf2*2][0]=q[0]; b[nf2*2][1]=q[2]; b[nf2*2+1][0]=q[1]; b[nf2*2+1][1]=q[3];
                }
            } else {
#pragma unroll
                for(int nf2=0;nf2<2;nf2++){
                    int r=k0+8*((lane>>3)&1)+(lane&7);
                    int c=((wn*32+nf2*16)>>3)+(lane>>4);
                    uint32_t q[4]; ldsm4t(q, bs + r*256 + ((c^(r&7))<<4));
                    b[nf2*2][0]=q[0]; b[nf2*2][1]=q[1]; b[nf2*2+1][0]=q[2]; b[nf2*2+1][1]=q[3];
                }
            }
#pragma unroll
            for(int mf=0;mf<4;mf++)
#pragma unroll
                for(int nf=0;nf<4;nf++)
                    mma16816(acc[mf][nf], a[mf], b[nf]);
        }
    }
}

// ---- GEMM kernels ----
__global__ void __launch_bounds__(256) mm_qk(
    const __nv_bfloat16* __restrict__ Xh, const __nv_bfloat16* __restrict__ Wqk,
    const float* __restrict__ bq, const float* __restrict__ bk,
    __nv_bfloat16* __restrict__ qh, __nv_bfloat16* __restrict__ kh)
{
    extern __shared__ __align__(1024) char smem[];
    int z=blockIdx.z;
    const __nv_bfloat16* A = Xh + (size_t)blockIdx.y*128*D_;
    const __nv_bfloat16* Bm = Wqk + (size_t)z*D_*D_ + blockIdx.x*128;
    float acc[4][4][4]={};
    mm_core<true>(A,Bm,acc,smem);
    const float* bias = z? bk:bq;
    __nv_bfloat16* outp = z? kh:qh;
    int wid=threadIdx.x>>5, lane=threadIdx.x&31, wm=wid>>2, wn=wid&3;
    size_t m0=(size_t)blockIdx.y*128 + wm*64 + lane/4;
    int n0=blockIdx.x*128 + wn*32 + (lane%4)*2;
#pragma unroll
    for(int mf=0;mf<4;mf++)
#pragma unroll
    for(int nf=0;nf<4;nf++){
        int n=n0+nf*8; size_t m=m0+mf*16;
        float b0=bias[n], b1=bias[n+1];
        *(uint32_t*)(outp+m*D_+n)     = cvt2(acc[mf][nf][1]+b1, acc[mf][nf][0]+b0);
        *(uint32_t*)(outp+(m+8)*D_+n) = cvt2(acc[mf][nf][3]+b1, acc[mf][nf][2]+b0);
    }
}

__global__ void __launch_bounds__(256) mm_sc(
    const __nv_bfloat16* __restrict__ qh, const __nv_bfloat16* __restrict__ kh,
    float* __restrict__ sc)
{
    extern __shared__ __align__(1024) char smem[];
    int z=blockIdx.z;
    const __nv_bfloat16* A = qh + (size_t)z*P_*D_ + (size_t)blockIdx.y*128*D_;
    const __nv_bfloat16* Bm = kh + (size_t)z*P_*D_ + (size_t)blockIdx.x*128*D_;
    float acc[4][4][4]={};
    mm_core<false>(A,Bm,acc,smem);
    int wid=threadIdx.x>>5, lane=threadIdx.x&31, wm=wid>>2, wn=wid&3;
    size_t m0=(size_t)blockIdx.y*128 + wm*64 + lane/4;
    int n0=blockIdx.x*128 + wn*32 + (lane%4)*2;
    float* C = sc + (size_t)z*P_*P_;
#pragma unroll
    for(int mf=0;mf<4;mf++)
#pragma unroll
    for(int nf=0;nf<4;nf++){
        int n=n0+nf*8; size_t m=m0+mf*16;
        *(float2*)(C+m*P_+n)     = make_float2(acc[mf][nf][0], acc[mf][nf][1]);
        *(float2*)(C+(m+8)*P_+n) = make_float2(acc[mf][nf][2], acc[mf][nf][3]);
    }
}

// ---- prep ----
__global__ void conv_x(const float4* __restrict__ X, uint2* __restrict__ hi)
{
    size_t i=(size_t)blockIdx.x*1024+threadIdx.x;
    float4 x=X[i];
    uint2 o;
    o.x=cvt2(x.y,x.x); o.y=cvt2(x.w,x.z);
    hi[i]=o;
}

__global__ void conv_wqk(const float* __restrict__ Wq,const float* __restrict__ Wk,__nv_bfloat16* __restrict__ out)
{
    size_t i=(size_t)blockIdx.x*1024+threadIdx.x;
    const size_t M=(size_t)D_*D_;
    out[i]=__float2bfloat16(i<M ? Wq[i] : Wk[i-M]);
}

__global__ void zero_f(float* p){ p[(size_t)blockIdx.x*blockDim.x+threadIdx.x]=0.f; }

// ---- fused softmax + column-mean -> attn_weights (attn never materialized) ----
__global__ __launch_bounds__(256) void softmax_colsum(const float* __restrict__ sc, float* __restrict__ aw, float scale)
{
    __shared__ float colacc[P_];
    int b=blockIdx.y, wid=threadIdx.x>>5, lane=threadIdx.x&31, tid=threadIdx.x;
#pragma unroll
    for(int i=0;i<8;i++) colacc[tid+256*i]=0.f;
    __syncthreads();

    const float* rp=sc+((size_t)b*P_+blockIdx.x*8+wid)*P_;
    float v[64];
#pragma unroll
    for(int i=0;i<64;i++) v[i]=rp[lane+32*i]*scale;
    float m=-INFINITY;
#pragma unroll
    for(int i=0;i<64;i++) m=fmaxf(m,v[i]);
#pragma unroll
    for(int o=16;o>0;o>>=1) m=fmaxf(m,__shfl_xor_sync(~0u,m,o));
    float s=0.f;
#pragma unroll
    for(int i=0;i<64;i++){ v[i]=__expf(v[i]-m); s+=v[i]; }
#pragma unroll
    for(int o=16;o>0;o>>=1) s+=__shfl_xor_sync(~0u,s,o);
    float rinv=1.f/s;
#pragma unroll
    for(int i=0;i<64;i++) atomicAdd(&colacc[lane+32*i], v[i]*rinv);
    __syncthreads();
#pragma unroll
    for(int i=0;i<8;i++) atomicAdd(&aw[b*P_+tid+256*i], colacc[tid+256*i]*(1.f/(float)P_));
}

// ---- xw = aw @ X  (per batch, fp32, streaming X once) ----
__global__ __launch_bounds__(1024) void awx_kernel(
    const float* __restrict__ aw,const float* __restrict__ X,float* __restrict__ xw)
{
    int b=blockIdx.y, qc=blockIdx.x*256;
    __shared__ float s_aw[256];
    if(threadIdx.x<256) s_aw[threadIdx.x]=aw[b*P_+qc+threadIdx.x];
    __syncthreads();
    float acc=0.f;
    const float* xb=X+((size_t)b*P_+qc)*D_+threadIdx.x;
#pragma unroll 4
    for(int q=0;q<256;q++) acc+=s_aw[q]*xb[(size_t)q*D_];
    atomicAdd(&xw[b*D_+threadIdx.x],acc);
}

// ---- weighted = xw @ Wv + bv  (fp32, exact) ----
__global__ __launch_bounds__(1024) void projv_kernel(
    const float* __restrict__ xw,const float* __restrict__ Wv,const float* __restrict__ bv,
    float* __restrict__ wt)
{
    int b=blockIdx.x, n=threadIdx.x;
    __shared__ float xs[D_];
    xs[n]=xw[b*D_+n];
    __syncthreads();
    float acc=bv[n];
    for(int k=0;k<D_;k++) acc+=xs[k]*Wv[(size_t)k*D_+n];
    wt[b*D_+n]=acc;
}

__device__ __forceinline__ float block_sum(float v,float* red)
{
#pragma unroll
    for(int o=16;o>0;o>>=1) v+=__shfl_xor_sync(~0u,v,o);
    int w=threadIdx.x>>5,l=threadIdx.x&31;
    if(l==0) red[w]=v;
    __syncthreads();
    if(w==0){
        float r=(threadIdx.x<(blockDim.x>>5))?red[threadIdx.x]:0.f;
#pragma unroll
        for(int o=16;o>0;o>>=1) r+=__shfl_xor_sync(~0u,r,o);
        if(l==0) red[0]=r;
    }
    __syncthreads();
    float out=red[0];
    __syncthreads();
    return out;
}

__global__ __launch_bounds__(1024) void mlp_kernel(
    const float* __restrict__ wt,const float* __restrict__ thum,const float* __restrict__ text,
    const float* peW1,const float* peb1,const float* peg,const float* pebt,const float* peW2,const float* peb2,
    const float* teW1,const float* teb1,const float* teg,const float* tebt,const float* teW2,const float* teb2,
    const float* thW1,const float* thb1,const float* thg,const float* thbt,const float* thW2,const float* thb2,
    float* __restrict__ feats)
{
    int row=blockIdx.x, job=blockIdx.y;
    const float *x,*W1,*b1,*g,*bt,*W2,*b2; int din;
    if(job==0){x=wt+row*D_;din=D_;W1=peW1;b1=peb1;g=peg;bt=pebt;W2=peW2;b2=peb2;}
    else if(job==1){x=thum+row*D_;din=D_;W1=thW1;b1=thb1;g=thg;bt=thbt;W2=thW2;b2=thb2;}
    else if(job==2){x=text+row*3*TD_+TD_;din=TD_;W1=teW1;b1=teb1;g=teg;bt=tebt;W2=teW2;b2=teb2;}
    else{x=text+row*3*TD_+2*TD_;din=TD_;W1=teW1;b1=teb1;g=teg;bt=tebt;W2=teW2;b2=teb2;}
    __shared__ float xs[1024], hs[1024], red[32];
    int tid=threadIdx.x;
    if(tid<din) xs[tid]=x[tid];
    __syncthreads();
    float acc=b1[tid];
    for(int i=0;i<din;i++) acc+=xs[i]*W1[(size_t)i*1024+tid];
    float h=fmaxf(acc,0.f);
    float s1=block_sum(h,red), s2=block_sum(h*h,red);
    float mu=s1*(1.f/1024.f), var=s2*(1.f/1024.f)-mu*mu, rstd=rsqrtf(var+EPS_);
    hs[tid]=(h-mu)*rstd*g[tid]+bt[tid];
    __syncthreads();
    float o=0.f;
    if(tid<PR_){
        float a2=b2[tid];
        for(int i=0;i<1024;i++) a2+=hs[i]*W2[(size_t)i*PR_+tid];
        o=fmaxf(a2,0.f);
    }
    float nrm=block_sum(o*o,red);
    if(tid<PR_) feats[((size_t)job*B_+row)*PR_+tid]=o*rsqrtf(nrm);
}

__global__ void logits_kernel(const float* __restrict__ feats,const float* __restrict__ ls_p,float* __restrict__ out)
{
    int j=threadIdx.x,i=threadIdx.y;
    float ls=expf(ls_p[0]);
    const float* pf=feats; const float* tf=feats+B_*PR_;
    const float* of=feats+2*B_*PR_; const float* hf=feats+3*B_*PR_;
    float lt=0.f,lp=0.f;
    for(int d=0;d<PR_;d++){ lt+=tf[i*PR_+d]*of[j*PR_+d]; lp+=pf[i*PR_+d]*hf[j*PR_+d]; }
    lt*=ls; lp*=ls;
    out[i*32+j]=lt; out[1024+i*32+j]=lp; out[2048+j*32+i]=lt; out[3072+j*32+i]=lp;
}

extern "C" void kernel_launch(void* const* d_in, const int* in_sizes, int n_in,
                              void* d_out, int out_size)
{
    const float* thum=(const float*)d_in[0];
    const float* patch=(const float*)d_in[1];
    const float* text=(const float*)d_in[2];
    const float* Wq=(const float*)d_in[3]; const float* bq=(const float*)d_in[4];
    const float* Wk=(const float*)d_in[5]; const float* bk=(const float*)d_in[6];
    const float* Wv=(const float*)d_in[7]; const float* bv=(const float*)d_in[8];
    const float* peW1=(const float*)d_in[9];  const float* peb1=(const float*)d_in[10];
    const float* peg =(const float*)d_in[11]; const float* pebt=(const float*)d_in[12];
    const float* peW2=(const float*)d_in[13]; const float* peb2=(const float*)d_in[14];
    const float* teW1=(const float*)d_in[15]; const float* teb1=(const float*)d_in[16];
    const float* teg =(const float*)d_in[17]; const float* tebt=(const float*)d_in[18];
    const float* teW2=(const float*)d_in[19]; const float* teb2=(const float*)d_in[20];
    const float* thW1=(const float*)d_in[21]; const float* thb1=(const float*)d_in[22];
    const float* thg =(const float*)d_in[23]; const float* thbt=(const float*)d_in[24];
    const float* thW2=(const float*)d_in[25]; const float* thb2=(const float*)d_in[26];
    const float* logit_scale=(const float*)d_in[27];

    float* out=(float*)d_out;
    float* aw_out=out+4096;

    __nv_bfloat16 *xh,*qh,*kh,*wqk;
    float *sc,*xw,*wtd,*ft;
    cudaGetSymbolAddress((void**)&xh,g_xh);
    cudaGetSymbolAddress((void**)&qh,g_qh);
    cudaGetSymbolAddress((void**)&kh,g_kh);
    cudaGetSymbolAddress((void**)&wqk,g_wqk);
    cudaGetSymbolAddress((void**)&sc,g_scores);
    cudaGetSymbolAddress((void**)&xw,g_xw);
    cudaGetSymbolAddress((void**)&wtd,g_weighted);
    cudaGetSymbolAddress((void**)&ft,g_feats);

    const int SMEM=3*STG_BYTES; // 48KB

    // prep
    conv_x<<<16384,1024>>>((const float4*)patch,(uint2*)xh);
    conv_wqk<<<2048,1024>>>(Wq,Wk,wqk);

    // GEMMs
    mm_qk<<<dim3(D_/128,(B_*P_)/128,2),256,SMEM>>>(xh,wqk,bq,bk,qh,kh);
    mm_sc<<<dim3(P_/128,P_/128,B_),256,SMEM>>>(qh,kh,sc);

    // softmax + column mean (directly into output)
    zero_f<<<64,1024>>>(aw_out);
    softmax_colsum<<<dim3(P_/8,B_),256>>>(sc,aw_out,1.f/32.f);

    // weighted = (aw @ X) @ Wv + bv   — v never materialized, exact fp32
    zero_f<<<32,1024>>>(xw);
    awx_kernel<<<dim3(P_/256,B_),1024>>>(aw_out,patch,xw);
    projv_kernel<<<B_,1024>>>(xw,Wv,bv,wtd);

    // MLPs + logits
    mlp_kernel<<<dim3(B_,4),1024>>>(wtd,thum,text,
        peW1,peb1,peg,pebt,peW2,peb2,
        teW1,teb1,teg,tebt,teW2,teb2,
        thW1,thb1,thg,thbt,thW2,thb2,ft);
    logits_kernel<<<1,dim3(32,32)>>>(ft,logit_scale,out);
}

// round 7
// speedup vs baseline: 3.6422x; 1.0035x over previous
#include <cuda_runtime.h>
#include <cuda_bf16.h>
#include <math.h>
#include <cstdint>

#define B_ 32
#define P_ 2048
#define D_ 1024
#define TD_ 768
#define PR_ 512
#define EPS_ 1e-5f

__device__ __align__(256) __nv_bfloat16 g_xh[(size_t)B_*P_*D_];
__device__ __align__(256) __nv_bfloat16 g_qh[(size_t)B_*P_*D_];
__device__ __align__(256) __nv_bfloat16 g_kh[(size_t)B_*P_*D_];
__device__ __align__(256) __nv_bfloat16 g_wqk[2*(size_t)D_*D_];
__device__ __align__(256) float g_e[(size_t)B_*P_*P_];     // exp(scores)
__device__ float g_Z[B_*P_];
__device__ float g_rinv[B_*P_];
__device__ float g_xw[B_*D_];
__device__ float g_weighted[B_*D_];
__device__ float g_feats[4*B_*PR_];

// ---- helpers ----
__device__ __forceinline__ uint32_t smem_u32(const void* p){uint32_t a;asm("{.reg .u64 t; cvta.to.shared.u64 t,%1; cvt.u32.u64 %0,t;}":"=r"(a):"l"(p));return a;}
__device__ __forceinline__ void cpa16(uint32_t s,const void* g){asm volatile("cp.async.cg.shared.global [%0],[%1],16;"::"r"(s),"l"(g));}
__device__ __forceinline__ void cpa_commit(){asm volatile("cp.async.commit_group;");}
template<int N> __device__ __forceinline__ void cpa_wait(){asm volatile("cp.async.wait_group %0;"::"n"(N));}
__device__ __forceinline__ void ldsm4(uint32_t* r,uint32_t a){
    asm volatile("ldmatrix.sync.aligned.m8n8.x4.shared.b16 {%0,%1,%2,%3},[%4];":"=r"(r[0]),"=r"(r[1]),"=r"(r[2]),"=r"(r[3]):"r"(a));
}
__device__ __forceinline__ void ldsm4t(uint32_t* r,uint32_t a){
    asm volatile("ldmatrix.sync.aligned.m8n8.x4.trans.shared.b16 {%0,%1,%2,%3},[%4];":"=r"(r[0]),"=r"(r[1]),"=r"(r[2]),"=r"(r[3]):"r"(a));
}
__device__ __forceinline__ void mma16816(float* c,const uint32_t* a,const uint32_t* b){
    asm volatile("mma.sync.aligned.m16n8k16.row.col.f32.bf16.bf16.f32 {%0,%1,%2,%3},{%4,%5,%6,%7},{%8,%9},{%0,%1,%2,%3};"
      :"+f"(c[0]),"+f"(c[1]),"+f"(c[2]),"+f"(c[3])
      :"r"(a[0]),"r"(a[1]),"r"(a[2]),"r"(a[3]),"r"(b[0]),"r"(b[1]));
}
__device__ __forceinline__ uint32_t cvt2(float hi,float lo){uint32_t r;asm("cvt.rn.bf16x2.f32 %0,%1,%2;":"=r"(r):"f"(hi),"f"(lo));return r;}

// ---- mma.sync core (unchanged from R6): acc[128x128] = A[128,1024] @ B^T ----
#define STG_BYTES 16384

template<bool BTRANS>
__device__ __forceinline__ void mm_core(
    const __nv_bfloat16* A, const __nv_bfloat16* Bm,
    float acc[4][4][4], char* smem)
{
    const int tid=threadIdx.x, wid=tid>>5, lane=tid&31;
    const int wm=wid>>2, wn=wid&3;
    const uint32_t sb=smem_u32(smem);

    auto fill=[&](int stg,int t){
        const char* Ab=(const char*)A;
        const char* Bb=(const char*)Bm;
        uint32_t as=sb+stg*STG_BYTES, bs=as+8192;
#pragma unroll
        for(int i=0;i<2;i++){
            int j=tid+256*i, r=j>>2, c=j&3;
            cpa16(as + r*64 + ((c^((r>>1)&3))<<4), Ab + (size_t)r*2048 + t*64 + c*16);
        }
        if(!BTRANS){
#pragma unroll
            for(int i=0;i<2;i++){
                int j=tid+256*i, r=j>>2, c=j&3;
                cpa16(bs + r*64 + ((c^((r>>1)&3))<<4), Bb + (size_t)r*2048 + t*64 + c*16);
            }
        } else {
#pragma unroll
            for(int i=0;i<2;i++){
                int j=tid+256*i, r=j>>4, c=j&15;
                cpa16(bs + r*256 + ((c^(r&7))<<4), Bb + (size_t)(t*32+r)*2048 + c*16);
            }
        }
        cpa_commit();
    };

    const int T=32;
    fill(0,0); fill(1,1);
    for(int tau=0;tau<T;tau++){
        int s=tau%3;
        cpa_wait<1>();
        __syncthreads();
        if(tau+2<T) fill((tau+2)%3, tau+2);
        uint32_t as=sb+s*STG_BYTES, bs=as+8192;
#pragma unroll
        for(int k0=0;k0<32;k0+=16){
            uint32_t a[4][4];
#pragma unroll
            for(int mf=0;mf<4;mf++){
                int r=wm*64+mf*16+(lane&15);
                int c=(k0>>3)+(lane>>4);
                ldsm4(a[mf], as + r*64 + ((c^((r>>1)&3))<<4));
            }
            uint32_t b[4][2];
            if(!BTRANS){
#pragma unroll
                for(int nf2=0;nf2<2;nf2++){
                    int r=wn*32+nf2*16+8*((lane>>3)&1)+(lane&7);
                    int c=(k0>>3)+(lane>>4);
                    uint32_t q[4]; ldsm4(q, bs + r*64 + ((c^((r>>1)&3))<<4));
                    b[nf2*2][0]=q[0]; b[nf2*2][1]=q[2]; b[nf2*2+1][0]=q[1]; b[nf2*2+1][1]=q[3];
                }
            } else {
#pragma unroll
                for(int nf2=0;nf2<2;nf2++){
                    int r=k0+8*((lane>>3)&1)+(lane&7);
                    int c=((wn*32+nf2*16)>>3)+(lane>>4);
                    uint32_t q[4]; ldsm4t(q, bs + r*256 + ((c^(r&7))<<4));
                    b[nf2*2][0]=q[0]; b[nf2*2][1]=q[1]; b[nf2*2+1][0]=q[2]; b[nf2*2+1][1]=q[3];
                }
            }
#pragma unroll
            for(int mf=0;mf<4;mf++)
#pragma unroll
                for(int nf=0;nf<4;nf++)
                    mma16816(acc[mf][nf], a[mf], b[nf]);
        }
    }
}

// ---- GEMM 1: q,k projections ----
__global__ void __launch_bounds__(256) mm_qk(
    const __nv_bfloat16* __restrict__ Xh, const __nv_bfloat16* __restrict__ Wqk,
    const float* __restrict__ bq, const float* __restrict__ bk,
    __nv_bfloat16* __restrict__ qh, __nv_bfloat16* __restrict__ kh)
{
    extern __shared__ __align__(1024) char smem[];
    int z=blockIdx.z;
    const __nv_bfloat16* A = Xh + (size_t)blockIdx.y*128*D_;
    const __nv_bfloat16* Bm = Wqk + (size_t)z*D_*D_ + blockIdx.x*128;
    float acc[4][4][4]={};
    mm_core<true>(A,Bm,acc,smem);
    const float* bias = z? bk:bq;
    __nv_bfloat16* outp = z? kh:qh;
    int wid=threadIdx.x>>5, lane=threadIdx.x&31, wm=wid>>2, wn=wid&3;
    size_t m0=(size_t)blockIdx.y*128 + wm*64 + lane/4;
    int n0=blockIdx.x*128 + wn*32 + (lane%4)*2;
#pragma unroll
    for(int mf=0;mf<4;mf++)
#pragma unroll
    for(int nf=0;nf<4;nf++){
        int n=n0+nf*8; size_t m=m0+mf*16;
        float b0=bias[n], b1=bias[n+1];
        *(uint32_t*)(outp+m*D_+n)     = cvt2(acc[mf][nf][1]+b1, acc[mf][nf][0]+b0);
        *(uint32_t*)(outp+(m+8)*D_+n) = cvt2(acc[mf][nf][3]+b1, acc[mf][nf][2]+b0);
    }
}

// ---- GEMM 2: e = exp(q@k^T * scale), plus row-sum partials into Z ----
__global__ void __launch_bounds__(256) mm_sc(
    const __nv_bfloat16* __restrict__ qh, const __nv_bfloat16* __restrict__ kh,
    float* __restrict__ e, float* __restrict__ Z)
{
    extern __shared__ __align__(1024) char smem[];
    int z=blockIdx.z;
    const __nv_bfloat16* A = qh + (size_t)z*P_*D_ + (size_t)blockIdx.y*128*D_;
    const __nv_bfloat16* Bm = kh + (size_t)z*P_*D_ + (size_t)blockIdx.x*128*D_;
    float acc[4][4][4]={};
    mm_core<false>(A,Bm,acc,smem);

    const float sl2e = (1.f/32.f)*1.44269504f;   // scale * log2(e)
    int wid=threadIdx.x>>5, lane=threadIdx.x&31, wm=wid>>2, wn=wid&3;
    size_t m0=(size_t)blockIdx.y*128 + wm*64 + lane/4;
    int n0=blockIdx.x*128 + wn*32 + (lane%4)*2;
    float* C = e + (size_t)z*P_*P_;
    float* Zb = Z + z*P_;

    float rp[4][2]={};
#pragma unroll
    for(int mf=0;mf<4;mf++)
#pragma unroll
    for(int nf=0;nf<4;nf++){
        int n=n0+nf*8; size_t m=m0+mf*16;
        float e0=exp2f(acc[mf][nf][0]*sl2e);
        float e1=exp2f(acc[mf][nf][1]*sl2e);
        float e2=exp2f(acc[mf][nf][2]*sl2e);
        float e3=exp2f(acc[mf][nf][3]*sl2e);
        *(float2*)(C+m*P_+n)     = make_float2(e0,e1);
        *(float2*)(C+(m+8)*P_+n) = make_float2(e2,e3);
        rp[mf][0]+=e0+e1; rp[mf][1]+=e2+e3;
    }
    // reduce row partials over the 4 lanes sharing a row, then atomic to Z
#pragma unroll
    for(int mf=0;mf<4;mf++)
#pragma unroll
    for(int h=0;h<2;h++){
        float v=rp[mf][h];
        v+=__shfl_xor_sync(~0u,v,1);
        v+=__shfl_xor_sync(~0u,v,2);
        if((lane&3)==0) atomicAdd(&Zb[m0+mf*16+h*8], v);
    }
}

// ---- prep ----
__global__ void conv_x(const float4* __restrict__ X, uint2* __restrict__ hi)
{
    size_t i=(size_t)blockIdx.x*1024+threadIdx.x;
    float4 x=X[i];
    uint2 o;
    o.x=cvt2(x.y,x.x); o.y=cvt2(x.w,x.z);
    hi[i]=o;
}

__global__ void conv_wqk(const float* __restrict__ Wq,const float* __restrict__ Wk,__nv_bfloat16* __restrict__ out)
{
    size_t i=(size_t)blockIdx.x*1024+threadIdx.x;
    const size_t M=(size_t)D_*D_;
    out[i]=__float2bfloat16(i<M ? Wq[i] : Wk[i-M]);
}

__global__ void zero_f(float* p){ p[(size_t)blockIdx.x*blockDim.x+threadIdx.x]=0.f; }

__global__ void recip_kernel(const float* __restrict__ Z, float* __restrict__ rinv)
{
    int i=blockIdx.x*1024+threadIdx.x;
    rinv[i]=1.f/Z[i];
}

// ---- aw_j = (1/P) * sum_r e[r][j] * rinv[r] ----
__global__ __launch_bounds__(256) void colsum_kernel(
    const float* __restrict__ e, const float* __restrict__ rinv, float* __restrict__ aw)
{
    __shared__ float rv[P_];
    int b=blockIdx.y, tid=threadIdx.x;
    for(int i=tid;i<P_;i+=256) rv[i]=rinv[b*P_+i];
    __syncthreads();
    int j=blockIdx.x*256+tid;
    const float* base=e+(size_t)b*P_*P_+j;
    float acc=0.f;
    for(int r=0;r<P_;r++) acc+=base[(size_t)r*P_]*rv[r];
    aw[b*P_+j]=acc*(1.f/(float)P_);
}

// ---- xw = aw @ X (bf16 X, fp32 accum) ----
__global__ __launch_bounds__(1024) void awx_kernel(
    const float* __restrict__ aw,const __nv_bfloat16* __restrict__ Xh,float* __restrict__ xw)
{
    int b=blockIdx.y, qc=blockIdx.x*256;
    __shared__ float s_aw[256];
    if(threadIdx.x<256) s_aw[threadIdx.x]=aw[b*P_+qc+threadIdx.x];
    __syncthreads();
    float acc=0.f;
    const __nv_bfloat16* xb=Xh+((size_t)b*P_+qc)*D_+threadIdx.x;
#pragma unroll 4
    for(int q=0;q<256;q++) acc+=s_aw[q]*__bfloat162float(xb[(size_t)q*D_]);
    atomicAdd(&xw[b*D_+threadIdx.x],acc);
}

// ---- weighted = xw @ Wv + bv (fp32 exact) ----
__global__ __launch_bounds__(1024) void projv_kernel(
    const float* __restrict__ xw,const float* __restrict__ Wv,const float* __restrict__ bv,
    float* __restrict__ wt)
{
    int b=blockIdx.x, n=threadIdx.x;
    __shared__ float xs[D_];
    xs[n]=xw[b*D_+n];
    __syncthreads();
    float acc=bv[n];
    for(int k=0;k<D_;k++) acc+=xs[k]*Wv[(size_t)k*D_+n];
    wt[b*D_+n]=acc;
}

__device__ __forceinline__ float block_sum(float v,float* red)
{
#pragma unroll
    for(int o=16;o>0;o>>=1) v+=__shfl_xor_sync(~0u,v,o);
    int w=threadIdx.x>>5,l=threadIdx.x&31;
    if(l==0) red[w]=v;
    __syncthreads();
    if(w==0){
        float r=(threadIdx.x<(blockDim.x>>5))?red[threadIdx.x]:0.f;
#pragma unroll
        for(int o=16;o>0;o>>=1) r+=__shfl_xor_sync(~0u,r,o);
        if(l==0) red[0]=r;
    }
    __syncthreads();
    float out=red[0];
    __syncthreads();
    return out;
}

__global__ __launch_bounds__(1024) void mlp_kernel(
    const float* __restrict__ wt,const float* __restrict__ thum,const float* __restrict__ text,
    const float* peW1,const float* peb1,const float* peg,const float* pebt,const float* peW2,const float* peb2,
    const float* teW1,const float* teb1,const float* teg,const float* tebt,const float* teW2,const float* teb2,
    const float* thW1,const float* thb1,const float* thg,const float* thbt,const float* thW2,const float* thb2,
    float* __restrict__ feats)
{
    int row=blockIdx.x, job=blockIdx.y;
    const float *x,*W1,*b1,*g,*bt,*W2,*b2; int din;
    if(job==0){x=wt+row*D_;din=D_;W1=peW1;b1=peb1;g=peg;bt=pebt;W2=peW2;b2=peb2;}
    else if(job==1){x=thum+row*D_;din=D_;W1=thW1;b1=thb1;g=thg;bt=thbt;W2=thW2;b2=thb2;}
    else if(job==2){x=text+row*3*TD_+TD_;din=TD_;W1=teW1;b1=teb1;g=teg;bt=tebt;W2=teW2;b2=teb2;}
    else{x=text+row*3*TD_+2*TD_;din=TD_;W1=teW1;b1=teb1;g=teg;bt=tebt;W2=teW2;b2=teb2;}
    __shared__ float xs[1024], hs[1024], red[32];
    int tid=threadIdx.x;
    if(tid<din) xs[tid]=x[tid];
    __syncthreads();
    float acc=b1[tid];
    for(int i=0;i<din;i++) acc+=xs[i]*W1[(size_t)i*1024+tid];
    float h=fmaxf(acc,0.f);
    float s1=block_sum(h,red), s2=block_sum(h*h,red);
    float mu=s1*(1.f/1024.f), var=s2*(1.f/1024.f)-mu*mu, rstd=rsqrtf(var+EPS_);
    hs[tid]=(h-mu)*rstd*g[tid]+bt[tid];
    __syncthreads();
    float o=0.f;
    if(tid<PR_){
        float a2=b2[tid];
        for(int i=0;i<1024;i++) a2+=hs[i]*W2[(size_t)i*PR_+tid];
        o=fmaxf(a2,0.f);
    }
    float nrm=block_sum(o*o,red);
    if(tid<PR_) feats[((size_t)job*B_+row)*PR_+tid]=o*rsqrtf(nrm);
}

__global__ void logits_kernel(const float* __restrict__ feats,const float* __restrict__ ls_p,float* __restrict__ out)
{
    int j=threadIdx.x,i=threadIdx.y;
    float ls=expf(ls_p[0]);
    const float* pf=feats; const float* tf=feats+B_*PR_;
    const float* of=feats+2*B_*PR_; const float* hf=feats+3*B_*PR_;
    float lt=0.f,lp=0.f;
    for(int d=0;d<PR_;d++){ lt+=tf[i*PR_+d]*of[j*PR_+d]; lp+=pf[i*PR_+d]*hf[j*PR_+d]; }
    lt*=ls; lp*=ls;
    out[i*32+j]=lt; out[1024+i*32+j]=lp; out[2048+j*32+i]=lt; out[3072+j*32+i]=lp;
}

extern "C" void kernel_launch(void* const* d_in, const int* in_sizes, int n_in,
                              void* d_out, int out_size)
{
    const float* thum=(const float*)d_in[0];
    const float* patch=(const float*)d_in[1];
    const float* text=(const float*)d_in[2];
    const float* Wq=(const float*)d_in[3]; const float* bq=(const float*)d_in[4];
    const float* Wk=(const float*)d_in[5]; const float* bk=(const float*)d_in[6];
    const float* Wv=(const float*)d_in[7]; const float* bv=(const float*)d_in[8];
    const float* peW1=(const float*)d_in[9];  const float* peb1=(const float*)d_in[10];
    const float* peg =(const float*)d_in[11]; const float* pebt=(const float*)d_in[12];
    const float* peW2=(const float*)d_in[13]; const float* peb2=(const float*)d_in[14];
    const float* teW1=(const float*)d_in[15]; const float* teb1=(const float*)d_in[16];
    const float* teg =(const float*)d_in[17]; const float* tebt=(const float*)d_in[18];
    const float* teW2=(const float*)d_in[19]; const float* teb2=(const float*)d_in[20];
    const float* thW1=(const float*)d_in[21]; const float* thb1=(const float*)d_in[22];
    const float* thg =(const float*)d_in[23]; const float* thbt=(const float*)d_in[24];
    const float* thW2=(const float*)d_in[25]; const float* thb2=(const float*)d_in[26];
    const float* logit_scale=(const float*)d_in[27];

    float* out=(float*)d_out;
    float* aw_out=out+4096;

    __nv_bfloat16 *xh,*qh,*kh,*wqk;
    float *e,*Z,*rinv,*xw,*wtd,*ft;
    cudaGetSymbolAddress((void**)&xh,g_xh);
    cudaGetSymbolAddress((void**)&qh,g_qh);
    cudaGetSymbolAddress((void**)&kh,g_kh);
    cudaGetSymbolAddress((void**)&wqk,g_wqk);
    cudaGetSymbolAddress((void**)&e,g_e);
    cudaGetSymbolAddress((void**)&Z,g_Z);
    cudaGetSymbolAddress((void**)&rinv,g_rinv);
    cudaGetSymbolAddress((void**)&xw,g_xw);
    cudaGetSymbolAddress((void**)&wtd,g_weighted);
    cudaGetSymbolAddress((void**)&ft,g_feats);

    const int SMEM=3*STG_BYTES; // 48KB

    // prep
    conv_x<<<16384,1024>>>((const float4*)patch,(uint2*)xh);
    conv_wqk<<<2048,1024>>>(Wq,Wk,wqk);

    // q,k projections
    mm_qk<<<dim3(D_/128,(B_*P_)/128,2),256,SMEM>>>(xh,wqk,bq,bk,qh,kh);

    // scores + exp + row-sum partials (softmax max-free; exp overlapped with tensor)
    zero_f<<<64,1024>>>(Z);
    mm_sc<<<dim3(P_/128,P_/128,B_),256,SMEM>>>(qh,kh,e,Z);

    // rinv, then attn_weights = column mean of e * rinv (directly into output)
    recip_kernel<<<64,1024>>>(Z,rinv);
    colsum_kernel<<<dim3(P_/256,B_),256>>>(e,rinv,aw_out);

    // weighted = (aw @ X) @ Wv + bv
    zero_f<<<32,1024>>>(xw);
    awx_kernel<<<dim3(P_/256,B_),1024>>>(aw_out,xh,xw);
    projv_kernel<<<B_,1024>>>(xw,Wv,bv,wtd);

    // MLPs + logits
    mlp_kernel<<<dim3(B_,4),1024>>>(wtd,thum,text,
        peW1,peb1,peg,pebt,peW2,peb2,
        teW1,teb1,teg,tebt,teW2,teb2,
        thW1,thb1,thg,thbt,thW2,thb2,ft);
    logits_kernel<<<1,dim3(32,32)>>>(ft,logit_scale,out);
}